// round 12
// baseline (speedup 1.0000x reference)
#include <cuda_runtime.h>

// GAE fused single-pass scan, v12: zero smem, sparse fixup.
// Key fact: alive is monotone within a chunk => bits is a prefix mask, and
// E[popc(bits)] ~= 1 at p(done)=0.5. So write outputs directly in phase A
// (lines stay L2-dirty), and phase C RMW-fixes only the ~1 prefix entries.
// DRAM traffic stays compulsory: 134MB read + 67MB write.

#define T_STEPS 4096
#define NENV    2048
#define NCHUNK  256
#define CHUNK   16

#define GAMMA_C 0.99f
#define GD_C    (0.99f * 0.95f)

__device__ float2 g_PS[NCHUNK * NENV];    // (P, S) aggregate per (chunk, env)
__device__ int    g_flag[NCHUNK * NENV];  // monotone per-run publish counter

// ---------------------------------------------------------------------------
__global__ void __launch_bounds__(256) gae_fused(
    const float* __restrict__ rewards,
    const float* __restrict__ values,
    const float* __restrict__ next_values,
    const int*   __restrict__ next_dones,
    float* __restrict__ adv,
    float* __restrict__ ret)
{
    const int tid = threadIdx.x;
    const int e = blockIdx.x * blockDim.x + tid;           // env
    const int c = (NCHUNK - 1) - blockIdx.y;               // latest chunk = bid 0
    const int base = ((c + 1) * CHUNK - 1) * NENV + e;     // last timestep of chunk
    const int o = c * NENV + e;

    // Self-incrementing flag protocol: each slot is written once per run by
    // its owner only, so the owner's stale read f0 is the previous run's
    // uniform count; publish f0+1 and wait for peers to reach f0+1.
    const int f0 = ((volatile int*)g_flag)[o];
    const int fpub = f0 + 1;

    // ---- Phase A: backward scan; write outputs directly (normal stores ->
    //      L2-dirty for the sparse fixup). Inputs streamed once. ----
    float g = 0.0f, p = 1.0f;
    unsigned int bits = 0u;
    bool alive = true;

    #pragma unroll
    for (int t = 0; t < CHUNK; t++) {                      // t=0 is LAST timestep
        const int idx = base - t * NENV;
        const int   dd = __ldcs(&next_dones[idx]);
        const float rr = __ldcs(&rewards[idx]);
        const float nv = __ldcs(&next_values[idx]);
        const float vv = __ldcs(&values[idx]);

        const float nd = dd ? 0.0f : 1.0f;
        g = (rr + GAMMA_C * nv * nd - vv) + GD_C * nd * g;
        p *= GD_C * nd;
        alive = alive && (dd == 0);
        if (alive) bits |= (1u << t);

        adv[idx] = g;                                      // provisional (fix=0 case)
        ret[idx] = g + vv;
    }

    // ---- Publish aggregate ----
    g_PS[o] = make_float2(p, g);
    __threadfence();
    ((volatile int*)g_flag)[o] = fpub;

    // ---- Phase B: compose G from later chunks' aggregates.
    // Chunk all-alive w.p. 2^-16 => accP hits 0 after ~1 hop. ----
    float G = 0.0f;
    if (c < NCHUNK - 1) {
        float accP = 1.0f, accS = 0.0f;
        int w = o + NENV;                                  // next-later chunk, same env
        const int wend = NCHUNK * NENV;
        while (w < wend && accP > 1e-12f) {
            while (((volatile int*)g_flag)[w] != fpub) __nanosleep(40);
            __threadfence();                               // acquire
            const float2 ps = __ldcg(&g_PS[w]);
            accS += accP * ps.y;
            accP *= ps.x;
            w += NENV;
        }
        G = accS;
    }

    // ---- Phase C: sparse fixup. bits is a prefix mask (alive monotone);
    //      E[len] ~= 1. RMW hits L2 (lines just written by this block). ----
    if (G != 0.0f) {
        const int k = __popc(bits);                        // prefix length
        float pw = GD_C;
        for (int t = 0; t < k; t++) {
            const int idx = base - t * NENV;
            const float fix = pw * G;
            adv[idx] += fix;
            ret[idx] += fix;
            pw *= GD_C;
        }
    }
}

// ---------------------------------------------------------------------------
extern "C" void kernel_launch(void* const* d_in, const int* in_sizes, int n_in,
                              void* d_out, int out_size)
{
    const float* rewards     = (const float*)d_in[0];
    const float* values      = (const float*)d_in[1];
    const float* next_values = (const float*)d_in[2];
    const int*   next_dones  = (const int*)d_in[3];

    float* adv = (float*)d_out;
    float* ret = (float*)d_out + (size_t)T_STEPS * NENV;

    dim3 block(256);
    dim3 grid(NENV / 256, NCHUNK);   // (8, 256) = 2048 blocks
    gae_fused<<<grid, block>>>(rewards, values, next_values, next_dones, adv, ret);
}

// round 13
// speedup vs baseline: 1.3703x; 1.3703x over previous
#include <cuda_runtime.h>

// GAE fused single-pass scan, v13 = v11 with CHUNK 16 -> 8.
// smem (sS+sV) 16KB/block -> 6-7 blocks/SM (occ ~80%), attacking the
// outstanding-load limit. Lookback ~1 hop (chunk all-alive w.p. 2^-8).
// DRAM traffic = compulsory 134MB read + 67MB write.

#define T_STEPS 4096
#define NENV    2048
#define NCHUNK  512
#define CHUNK   8

#define GAMMA_C 0.99f
#define GD_C    (0.99f * 0.95f)

__device__ float2 g_PS[NCHUNK * NENV];    // (P, S) aggregate per (chunk, env)
__device__ int    g_flag[NCHUNK * NENV];  // monotone per-run publish counter

// ---------------------------------------------------------------------------
__global__ void __launch_bounds__(256) gae_fused(
    const float* __restrict__ rewards,
    const float* __restrict__ values,
    const float* __restrict__ next_values,
    const int*   __restrict__ next_dones,
    float* __restrict__ adv,
    float* __restrict__ ret)
{
    __shared__ float sS[CHUNK * 256];                      // 8KB: local scan value
    __shared__ float sV[CHUNK * 256];                      // 8KB: values

    const int tid = threadIdx.x;
    const int e = blockIdx.x * blockDim.x + tid;           // env
    const int c = (NCHUNK - 1) - blockIdx.y;               // latest chunk = bid 0
    const int base = ((c + 1) * CHUNK - 1) * NENV + e;     // last timestep of chunk
    const int o = c * NENV + e;

    // Self-incrementing flag protocol: each slot is written exactly once per
    // run, only by its owner, so the owner's stale read f0 is the previous
    // run's uniform count. Publish f0+1; wait for peers to reach f0+1.
    const int f0 = ((volatile int*)g_flag)[o];
    const int fpub = f0 + 1;

    // ---- Phase A: local backward scan; S,V -> smem; inputs streamed once ----
    float g = 0.0f, p = 1.0f;
    unsigned int bits = 0u;
    bool alive = true;

    #pragma unroll
    for (int t = 0; t < CHUNK; t++) {                      // t=0 is LAST timestep
        const int idx = base - t * NENV;
        const int   dd = __ldcs(&next_dones[idx]);
        const float rr = __ldcs(&rewards[idx]);
        const float nv = __ldcs(&next_values[idx]);
        const float vv = __ldcs(&values[idx]);

        const float nd = dd ? 0.0f : 1.0f;
        g = (rr + GAMMA_C * nv * nd - vv) + GD_C * nd * g;
        p *= GD_C * nd;
        alive = alive && (dd == 0);
        if (alive) bits |= (1u << t);
        sS[t * 256 + tid] = g;
        sV[t * 256 + tid] = vv;
    }

    // ---- Publish aggregate ----
    g_PS[o] = make_float2(p, g);
    __threadfence();
    ((volatile int*)g_flag)[o] = fpub;

    // ---- Phase B: compose G from later chunks' aggregates ----
    float G = 0.0f;
    if (c < NCHUNK - 1) {
        float accP = 1.0f, accS = 0.0f;
        int w = o + NENV;                                  // next-later chunk, same env
        const int wend = NCHUNK * NENV;
        while (w < wend && accP > 1e-12f) {
            while (((volatile int*)g_flag)[w] != fpub) __nanosleep(40);
            __threadfence();                               // acquire
            const float2 ps = __ldcg(&g_PS[w]);
            accS += accP * ps.y;
            accP *= ps.x;
            w += NENV;
        }
        G = accS;
    }

    // ---- Phase C: fixup from smem only; stream outputs exactly once ----
    float pw = GD_C;
    #pragma unroll
    for (int t = 0; t < CHUNK; t++) {
        const int idx = base - t * NENV;
        const float fix = ((bits >> t) & 1u) ? pw * G : 0.0f;
        const float a = sS[t * 256 + tid] + fix;
        __stcs(&adv[idx], a);
        __stcs(&ret[idx], a + sV[t * 256 + tid]);
        pw *= GD_C;
    }
}

// ---------------------------------------------------------------------------
extern "C" void kernel_launch(void* const* d_in, const int* in_sizes, int n_in,
                              void* d_out, int out_size)
{
    const float* rewards     = (const float*)d_in[0];
    const float* values      = (const float*)d_in[1];
    const float* next_values = (const float*)d_in[2];
    const int*   next_dones  = (const int*)d_in[3];

    float* adv = (float*)d_out;
    float* ret = (float*)d_out + (size_t)T_STEPS * NENV;

    dim3 block(256);
    dim3 grid(NENV / 256, NCHUNK);   // (8, 512) = 4096 blocks
    gae_fused<<<grid, block>>>(rewards, values, next_values, next_dones, adv, ret);
}

// round 14
// speedup vs baseline: 1.4014x; 1.0227x over previous
#include <cuda_runtime.h>

// GAE fused single-pass scan, v14 = v11 widened x2 (float2 env-pairs).
// LDG.64 input streams, STG.64 output streams; CHUNK 16->8 keeps smem at
// 32KB (sS+sV as float2). Self-incrementing flag lookback (aggregates are
// float4 per env-pair). DRAM traffic = compulsory 134MB R + 67MB W.

#define T_STEPS 4096
#define NENV    2048
#define NE2     (NENV / 2)     // 1024 env-pairs
#define NCHUNK  512
#define CHUNK   8

#define GAMMA_C 0.99f
#define GD_C    (0.99f * 0.95f)

__device__ float4 g_PS[NCHUNK * NE2];    // (P0,S0,P1,S1) per (chunk, env-pair)
__device__ int    g_flag[NCHUNK * NE2];  // monotone per-run publish counter

// ---------------------------------------------------------------------------
__global__ void __launch_bounds__(256) gae_fused(
    const float2* __restrict__ rewards,
    const float2* __restrict__ values,
    const float2* __restrict__ next_values,
    const int2*   __restrict__ next_dones,
    float2* __restrict__ adv,
    float2* __restrict__ ret)
{
    __shared__ float2 sS[CHUNK * 256];                     // 16KB
    __shared__ float2 sV[CHUNK * 256];                     // 16KB

    const int tid = threadIdx.x;
    const int e2 = blockIdx.x * blockDim.x + tid;          // env-pair
    const int c  = (NCHUNK - 1) - blockIdx.y;              // latest chunk = bid 0
    const int base = ((c + 1) * CHUNK - 1) * NE2 + e2;     // last timestep of chunk
    const int o = c * NE2 + e2;

    // Self-incrementing flag protocol (each slot written once per run, only
    // by its owner; owner's stale read f0 = previous run's uniform count).
    const int f0 = ((volatile int*)g_flag)[o];
    const int fpub = f0 + 1;

    // ---- Phase A: local backward scan (2 envs); S,V -> smem ----
    float g0 = 0.f, g1 = 0.f, p0 = 1.f, p1 = 1.f;
    unsigned int b0 = 0u, b1 = 0u;
    bool a0 = true, a1 = true;

    #pragma unroll
    for (int t = 0; t < CHUNK; t++) {                      // t=0 is LAST timestep
        const int idx = base - t * NE2;
        const int2   d  = __ldcs(&next_dones[idx]);
        const float2 r  = __ldcs(&rewards[idx]);
        const float2 nv = __ldcs(&next_values[idx]);
        const float2 v  = __ldcs(&values[idx]);

        const float nd0 = d.x ? 0.f : 1.f;
        const float nd1 = d.y ? 0.f : 1.f;
        g0 = (r.x + GAMMA_C * nv.x * nd0 - v.x) + GD_C * nd0 * g0;
        g1 = (r.y + GAMMA_C * nv.y * nd1 - v.y) + GD_C * nd1 * g1;
        p0 *= GD_C * nd0;
        p1 *= GD_C * nd1;
        a0 = a0 && (d.x == 0);
        a1 = a1 && (d.y == 0);
        if (a0) b0 |= (1u << t);
        if (a1) b1 |= (1u << t);
        sS[t * 256 + tid] = make_float2(g0, g1);
        sV[t * 256 + tid] = v;
    }

    // ---- Publish aggregate ----
    g_PS[o] = make_float4(p0, g0, p1, g1);
    __threadfence();
    ((volatile int*)g_flag)[o] = fpub;

    // ---- Phase B: compose G per env from later chunks' aggregates.
    // 8-step chunk all-alive w.p. 2^-8 => accP hits ~0 after ~1 hop. ----
    float G0 = 0.0f, G1 = 0.0f;
    if (c < NCHUNK - 1) {
        float aP0 = 1.f, aS0 = 0.f, aP1 = 1.f, aS1 = 0.f;
        int w = o + NE2;                                   // next-later chunk
        const int wend = NCHUNK * NE2;
        while (w < wend && (aP0 > 1e-12f || aP1 > 1e-12f)) {
            while (((volatile int*)g_flag)[w] != fpub) __nanosleep(40);
            __threadfence();                               // acquire
            const float4 ps = __ldcg(&g_PS[w]);
            aS0 += aP0 * ps.y;  aP0 *= ps.x;
            aS1 += aP1 * ps.w;  aP1 *= ps.z;
            w += NE2;
        }
        G0 = aS0;
        G1 = aS1;
    }

    // ---- Phase C: fixup from smem only; stream outputs exactly once ----
    float pw = GD_C;
    #pragma unroll
    for (int t = 0; t < CHUNK; t++) {
        const int idx = base - t * NE2;
        const float2 s = sS[t * 256 + tid];
        const float2 v = sV[t * 256 + tid];
        const float f0x = ((b0 >> t) & 1u) ? pw * G0 : 0.0f;
        const float f1x = ((b1 >> t) & 1u) ? pw * G1 : 0.0f;
        const float2 a = make_float2(s.x + f0x, s.y + f1x);
        __stcs(&adv[idx], a);
        __stcs(&ret[idx], make_float2(a.x + v.x, a.y + v.y));
        pw *= GD_C;
    }
}

// ---------------------------------------------------------------------------
extern "C" void kernel_launch(void* const* d_in, const int* in_sizes, int n_in,
                              void* d_out, int out_size)
{
    const float2* rewards     = (const float2*)d_in[0];
    const float2* values      = (const float2*)d_in[1];
    const float2* next_values = (const float2*)d_in[2];
    const int2*   next_dones  = (const int2*)d_in[3];

    float2* adv = (float2*)d_out;
    float2* ret = (float2*)((float*)d_out + (size_t)T_STEPS * NENV);

    dim3 block(256);
    dim3 grid(NE2 / 256, NCHUNK);   // (4, 512) = 2048 blocks
    gae_fused<<<grid, block>>>(rewards, values, next_values, next_dones, adv, ret);
}